// round 15
// baseline (speedup 1.0000x reference)
#include <cuda_runtime.h>
#include <cstdint>

namespace {
constexpr int T_STEPS = 64;
constexpr int S_DIM = 16;
constexpr int B_DIM = 2048;
constexpr int SB = S_DIM * B_DIM;  // 32768 rows
constexpr int R = 128;             // rows per block; warp-pair per 16 rows
constexpr int NT = 512;
// dynamic smem (floats): Wf 4096 + zsw 8192 + eps 2*8192 + red 16
constexpr int SMEM_FLOATS = 4096 + 8192 + 2 * 8192 + 16;
constexpr int SMEM_BYTES = SMEM_FLOATS * 4;  // ~114.8 KB
}

__device__ float g_cd[B_DIM * 64];  // context @ Wc, [B][Z]

__global__ void ctx_kernel(const float* __restrict__ context,
                           const float* __restrict__ Wc) {
    int idx = blockIdx.x * blockDim.x + threadIdx.x;
    int b = idx >> 6, z = idx & 63;
    float acc = 0.f;
#pragma unroll
    for (int c = 0; c < 64; ++c)
        acc = fmaf(context[b * 64 + c], Wc[c * 64 + z], acc);
    g_cd[idx] = acc;
}

using u64 = unsigned long long;
__device__ __forceinline__ u64 pack2(float x, float y) {
    u64 r; asm("mov.b64 %0, {%1, %2};" : "=l"(r) : "f"(x), "f"(y)); return r;
}
__device__ __forceinline__ void unpack2(u64 v, float& x, float& y) {
    asm("mov.b64 {%0, %1}, %2;" : "=f"(x), "=f"(y) : "l"(v));
}
__device__ __forceinline__ void ffma2(u64& d, u64 a, u64 b) {
    asm("fma.rn.f32x2 %0, %1, %2, %0;" : "+l"(d) : "l"(a), "l"(b));
}
__device__ __forceinline__ u64 ffma2n(u64 a, u64 b, u64 c) {
    u64 d; asm("fma.rn.f32x2 %0, %1, %2, %3;" : "=l"(d) : "l"(a), "l"(b), "l"(c));
    return d;
}
__device__ __forceinline__ u64 add2(u64 a, u64 b) {
    u64 d; asm("add.rn.f32x2 %0, %1, %2;" : "=l"(d) : "l"(a), "l"(b)); return d;
}
__device__ __forceinline__ u64 mul2(u64 a, u64 b) {
    u64 d; asm("mul.rn.f32x2 %0, %1, %2;" : "=l"(d) : "l"(a), "l"(b)); return d;
}
__device__ __forceinline__ void mma_tf32(float* d, uint32_t a0, uint32_t a1,
                                         uint32_t a2, uint32_t a3,
                                         uint32_t b0, uint32_t b1) {
    asm("mma.sync.aligned.m16n8k8.row.col.f32.tf32.tf32.f32 "
        "{%0,%1,%2,%3}, {%4,%5,%6,%7}, {%8,%9}, {%0,%1,%2,%3};"
        : "+f"(d[0]), "+f"(d[1]), "+f"(d[2]), "+f"(d[3])
        : "r"(a0), "r"(a1), "r"(a2), "r"(a3), "r"(b0), "r"(b1));
}
__device__ __forceinline__ void cp16(uint32_t dst, const void* src) {
    asm volatile("cp.async.cg.shared.global [%0], [%1], 16;" :: "r"(dst), "l"(src));
}
__device__ __forceinline__ void bar_pair(int id) {
    asm volatile("bar.sync %0, 64;" :: "r"(id) : "memory");
}
// swizzled offset (floats) of (row r, col c): 16B-chunk rotate per row
__device__ __forceinline__ int zoff(int r, int c) {
    return r * 64 + ((c + 4 * (r & 7)) & 63);
}

__global__ void __launch_bounds__(NT, 2) scan_kernel(
    const float* __restrict__ z0, const float* __restrict__ eps,
    const float* __restrict__ W, const float* __restrict__ bvec,
    const float* __restrict__ sigmas, float* __restrict__ out) {
    extern __shared__ float smem[];
    u64* Wf = (u64*)smem;             // 2048 pre-packed B fragments
    float* zsw = smem + 4096;         // z tile [128][64], zoff-swizzled
    float* epsb = smem + 12288;       // 2 x [128][64] eps tiles, zoff-swizzled
    float* red = smem + 28672;        // [16]

    const int tid = threadIdx.x;
    const int w = tid >> 5;           // 16 warps: pair p = w>>1, half hf = w&1
    const int l = tid & 31;
    const int p = w >> 1;
    const int hf = w & 1;
    const int a = l >> 2;
    const int b = l & 3;
    const int colb = 2 * b;
    const int nto = 4 * hf;           // my 4 nt tiles: nto..nto+3
    const int rA = p * 16 + a;
    const int rB = rA + 8;
    const int r0 = blockIdx.x * R;
    const int b0i = r0 & (B_DIM - 1);
    const float dt = 1.0f / T_STEPS;
    const u64 dt2 = pack2(dt, dt);
    const uint32_t eps_u32 = (uint32_t)__cvta_generic_to_shared(epsb);

    // Wf: B-fragment (ks,nt,lane) = (W[8ks+b][8nt+a], W[8ks+b+4][8nt+a]) tf32
#pragma unroll
    for (int it = 0; it < 2048 / NT; ++it) {
        int idx = tid + it * NT;
        int ks = idx >> 8, nt = (idx >> 5) & 7, ll = idx & 31;
        int aa = ll >> 2, bb = ll & 3;
        float w0 = W[(8 * ks + bb) * 64 + 8 * nt + aa];
        float w1 = W[(8 * ks + bb + 4) * 64 + 8 * nt + aa];
        uint32_t t0, t1;
        asm("cvt.rna.tf32.f32 %0, %1;" : "=r"(t0) : "f"(w0));
        asm("cvt.rna.tf32.f32 %0, %1;" : "=r"(t1) : "f"(w1));
        Wf[idx] = ((u64)t1 << 32) | t0;
    }

    float* zs_out = out + 1;  // 4B-aligned only: scalar global stores
    u64 esq2 = 0, usq2 = 0;
    u64 up2[2][4];            // [h][j], j over my 4 nt tiles

    // init: z0 (my rows x my col half) -> zsw + z0^2
#pragma unroll
    for (int j = 0; j < 4; ++j) {
        const int cg = colb + 8 * (nto + j);
#pragma unroll
        for (int h = 0; h < 2; ++h) {
            const int row = h ? rB : rA;
            u64 zz = *(const u64*)(z0 + (size_t)(r0 + row) * 64 + cg);
            ffma2(esq2, zz, zz);
            up2[h][j] = 0;
            *(u64*)(zsw + zoff(row, cg)) = zz;
        }
    }

    // prefetch eps(0): my pair rows x my chunk half (4 cp16/thread)
    {
        const float* src0 = eps + (size_t)r0 * 64;
#pragma unroll
        for (int it = 0; it < 4; ++it) {
            int id = it * 32 + l;                 // 0..127
            int row = p * 16 + (id >> 3);
            int ch = 8 * hf + (id & 7);
            cp16(eps_u32 + (uint32_t)(row * 64 + 4 * ((ch + (row & 7)) & 15)) * 4u,
                 src0 + (size_t)row * 64 + ch * 4);
        }
        asm volatile("cp.async.commit_group;");
    }
    __syncthreads();  // Wf + zsw visible (block-wide, once)

    // z_samples[0]: my 16 rows x my col half, coalesced
#pragma unroll
    for (int i = 0; i < 16; ++i) {
        const int row = p * 16 + i;
        __stcs(zs_out + (size_t)(r0 + row) * 64 + 32 * hf + l,
               zsw[zoff(row, 32 * hf + l)]);
    }

    const uint32_t* zswu = (const uint32_t*)zsw;
    u64 dtinvp2 = 0;

#pragma unroll 1
    for (int t = 0; t <= T_STEPS; ++t) {
        // prefetch eps(t+1)
        if (t + 1 < T_STEPS) {
            const float* src = eps + ((size_t)(t + 1) * SB + (size_t)r0) * 64;
            const uint32_t dst_u32 = eps_u32 + (uint32_t)(((t + 1) & 1) * 32768);
#pragma unroll
            for (int it = 0; it < 4; ++it) {
                int id = it * 32 + l;
                int row = p * 16 + (id >> 3);
                int ch = 8 * hf + (id & 7);
                cp16(dst_u32 + (uint32_t)(row * 64 + 4 * ((ch + (row & 7)) & 15)) * 4u,
                     src + (size_t)row * 64 + ch * 4);
            }
            asm volatile("cp.async.commit_group;");
        }

        // ctx-drift prefetch from L2 (latency covered by GEMM)
        u64 cdr[2][4];
        if (t < T_STEPS) {
#pragma unroll
            for (int j = 0; j < 4; ++j) {
                const int cg = colb + 8 * (nto + j);
#pragma unroll
                for (int h = 0; h < 2; ++h) {
                    const int row = h ? rB : rA;
                    cdr[h][j] =
                        *(const u64*)(g_cd + (size_t)(b0i + row) * 64 + cg);
                }
            }
        }

        // ---- GEMM: my 16 rows x my 32 drift cols via HMMA ----
        float acc[4][4];
#pragma unroll
        for (int j = 0; j < 4; ++j)
#pragma unroll
            for (int q = 0; q < 4; ++q) acc[j][q] = 0.f;
#pragma unroll
        for (int ks = 0; ks < 8; ++ks) {
            uint32_t a0 = zswu[zoff(rA, 8 * ks + b)];
            uint32_t a2 = zswu[zoff(rA, 8 * ks + b + 4)];
            uint32_t a1 = zswu[zoff(rB, 8 * ks + b)];
            uint32_t a3 = zswu[zoff(rB, 8 * ks + b + 4)];
#pragma unroll
            for (int j = 0; j < 4; ++j) {
                u64 bb = Wf[(ks * 8 + nto + j) * 32 + l];
                mma_tf32(acc[j], a0, a1, a2, a3, (uint32_t)bb,
                         (uint32_t)(bb >> 32));
            }
        }

        if (t == T_STEPS) {  // final completion of u(T-1)
#pragma unroll
            for (int j = 0; j < 4; ++j)
#pragma unroll
                for (int h = 0; h < 2; ++h) {
                    u64 d2 = pack2(acc[j][2 * h], acc[j][2 * h + 1]);
                    u64 u2 = ffma2n(d2, dtinvp2, up2[h][j]);
                    ffma2(usq2, u2, u2);
                }
            break;
        }

        bar_pair(p + 1);  // partner's GEMM reads done before zsw writes

        // eps(t) ready
        if (t + 1 < T_STEPS) {
            asm volatile("cp.async.wait_group 1;" ::: "memory");
        } else {
            asm volatile("cp.async.wait_group 0;" ::: "memory");
        }
        __syncwarp();

        // ---- elementwise phase (my rows x my cols) ----
        const float sig = __ldg(sigmas + t);
        const float stdv = sig * 0.125f;
        const float inv_std = 1.0f / stdv;
        const float dtinv = dt * inv_std;
        const u64 std2 = pack2(stdv, stdv);
        const u64 dtinv2 = pack2(dtinv, dtinv);
        const u64 ndtinv2 = pack2(-dtinv, -dtinv);
        const float* et = epsb + (t & 1) * 8192;
        const bool last = (t == T_STEPS - 1);

#pragma unroll
        for (int j = 0; j < 4; ++j) {
            const int cg = colb + 8 * (nto + j);
            float2 btv = __ldg((const float2*)(bvec + t * 64 + cg));
            u64 bt2 = pack2(btv.x, btv.y);
            u64 btd2 = mul2(bt2, dtinv2);
#pragma unroll
            for (int h = 0; h < 2; ++h) {
                const int row = h ? rB : rA;
                u64 d2 = pack2(acc[j][2 * h], acc[j][2 * h + 1]);
                u64 u2 = ffma2n(d2, dtinvp2, up2[h][j]);  // complete u(t-1)
                ffma2(usq2, u2, u2);
                u64 zp2 = *(const u64*)(zsw + zoff(row, cg));
                u64 e2 = *(const u64*)(et + zoff(row, cg));
                u64 mu2 = add2(d2, add2(cdr[h][j], bt2));
                u64 zn2 = ffma2n(e2, std2, ffma2n(mu2, dt2, zp2));
                up2[h][j] =
                    ffma2n(mu2, ndtinv2, add2(e2 ^ 0x8000000080000000ull, btd2));
                ffma2(esq2, e2, e2);
                if (last) ffma2(usq2, zn2, zn2);
                *(u64*)(zsw + zoff(row, cg)) = zn2;
            }
        }
        __syncwarp();  // zn2 cross-lane visible for the coalesced stores

        // ---- coalesced z_samples(t+1) stores (my rows x my half) ----
        float* zo = zs_out + (size_t)(t + 1) * SB * 64;
#pragma unroll
        for (int i = 0; i < 16; ++i) {
            const int row = p * 16 + i;
            __stcs(zo + (size_t)(r0 + row) * 64 + 32 * hf + l,
                   zsw[zoff(row, 32 * hf + l)]);
        }

        bar_pair(p + 1);  // zsw(t+1) complete before partner's next GEMM
        dtinvp2 = dtinv2;
    }

    // reduce lw = (0.5/S) * (esq - usq)
    float e0, e1, q0, q1;
    unpack2(esq2, e0, e1);
    unpack2(usq2, q0, q1);
    float lw = (e0 + e1) - (q0 + q1);
#pragma unroll
    for (int off = 16; off; off >>= 1)
        lw += __shfl_down_sync(0xffffffffu, lw, off);
    if (l == 0) red[w] = lw;
    __syncthreads();
    if (tid == 0) {
        float s = 0.f;
#pragma unroll
        for (int i = 0; i < 16; ++i) s += red[i];
        atomicAdd(out, (0.5f / S_DIM) * s);
    }
}

extern "C" void kernel_launch(void* const* d_in, const int* in_sizes, int n_in,
                              void* d_out, int out_size) {
    (void)in_sizes; (void)n_in; (void)out_size;
    const float* z0      = (const float*)d_in[0];
    const float* eps     = (const float*)d_in[1];
    const float* context = (const float*)d_in[2];
    const float* W       = (const float*)d_in[3];
    const float* Wc      = (const float*)d_in[4];
    const float* bvec    = (const float*)d_in[5];
    const float* sigmas  = (const float*)d_in[6];
    float* out = (float*)d_out;

    cudaFuncSetAttribute(scan_kernel,
                         cudaFuncAttributeMaxDynamicSharedMemorySize, SMEM_BYTES);
    cudaMemsetAsync(out, 0, sizeof(float));
    ctx_kernel<<<(B_DIM * 64) / 256, 256>>>(context, Wc);
    scan_kernel<<<SB / R, NT, SMEM_BYTES>>>(z0, eps, W, bvec, sigmas, out);
}

// round 16
// speedup vs baseline: 1.2816x; 1.2816x over previous
#include <cuda_runtime.h>
#include <cstdint>

namespace {
constexpr int T_STEPS = 64;
constexpr int S_DIM = 16;
constexpr int B_DIM = 2048;
constexpr int SB = S_DIM * B_DIM;  // 32768 rows
constexpr int R = 128;             // rows per block (1 chain/warp, 8 warps)
constexpr int NT = 256;
// dyn smem floats: Wf 2048 (8KB) + zbh 4096 (16KB) + eps 2*8192 (64KB) + red 8
constexpr int SMEM_FLOATS = 2048 + 4096 + 2 * 8192 + 8;
constexpr int SMEM_BYTES = SMEM_FLOATS * 4;  // ~88.1 KB
}

__device__ float g_cd[B_DIM * 64];  // context @ Wc, [B][Z]

__global__ void ctx_kernel(const float* __restrict__ context,
                           const float* __restrict__ Wc) {
    int idx = blockIdx.x * blockDim.x + threadIdx.x;
    int b = idx >> 6, z = idx & 63;
    float acc = 0.f;
#pragma unroll
    for (int c = 0; c < 64; ++c)
        acc = fmaf(context[b * 64 + c], Wc[c * 64 + z], acc);
    g_cd[idx] = acc;
}

using u64 = unsigned long long;
__device__ __forceinline__ u64 pack2(float x, float y) {
    u64 r; asm("mov.b64 %0, {%1, %2};" : "=l"(r) : "f"(x), "f"(y)); return r;
}
__device__ __forceinline__ void unpack2(u64 v, float& x, float& y) {
    asm("mov.b64 {%0, %1}, %2;" : "=f"(x), "=f"(y) : "l"(v));
}
__device__ __forceinline__ void ffma2(u64& d, u64 a, u64 b) {
    asm("fma.rn.f32x2 %0, %1, %2, %0;" : "+l"(d) : "l"(a), "l"(b));
}
__device__ __forceinline__ u64 ffma2n(u64 a, u64 b, u64 c) {
    u64 d; asm("fma.rn.f32x2 %0, %1, %2, %3;" : "=l"(d) : "l"(a), "l"(b), "l"(c));
    return d;
}
__device__ __forceinline__ u64 add2(u64 a, u64 b) {
    u64 d; asm("add.rn.f32x2 %0, %1, %2;" : "=l"(d) : "l"(a), "l"(b)); return d;
}
__device__ __forceinline__ u64 mul2(u64 a, u64 b) {
    u64 d; asm("mul.rn.f32x2 %0, %1, %2;" : "=l"(d) : "l"(a), "l"(b)); return d;
}
// m16n8k16 bf16 HMMA
__device__ __forceinline__ void mma_bf16(float* d, uint32_t a0, uint32_t a1,
                                         uint32_t a2, uint32_t a3,
                                         uint32_t b0, uint32_t b1) {
    asm("mma.sync.aligned.m16n8k16.row.col.f32.bf16.bf16.f32 "
        "{%0,%1,%2,%3}, {%4,%5,%6,%7}, {%8,%9}, {%0,%1,%2,%3};"
        : "+f"(d[0]), "+f"(d[1]), "+f"(d[2]), "+f"(d[3])
        : "r"(a0), "r"(a1), "r"(a2), "r"(a3), "r"(b0), "r"(b1));
}
// pack (lo, hi) floats -> bf16x2 u32 (lo in lower half)
__device__ __forceinline__ uint32_t bf2(float lo, float hi) {
    uint32_t p;
    asm("cvt.rn.bf16x2.f32 %0, %1, %2;" : "=r"(p) : "f"(hi), "f"(lo));
    return p;
}
__device__ __forceinline__ void cp16(uint32_t dst, const void* src) {
    asm volatile("cp.async.cg.shared.global [%0], [%1], 16;" :: "r"(dst), "l"(src));
}
// fp32 tile swizzle (floats): 16B-chunk rotate per row, 64 cols
__device__ __forceinline__ int zoff(int r, int c) {
    return r * 64 + ((c + 4 * (r & 7)) & 63);
}
// bf16x2 tile swizzle (u32 pairs): rotate per row, 32 pairs
__device__ __forceinline__ int zbi(int r, int pr) {
    return r * 32 + ((pr + 4 * (r & 7)) & 31);
}

__global__ void __launch_bounds__(NT, 2) scan_kernel(
    const float* __restrict__ z0, const float* __restrict__ eps,
    const float* __restrict__ W, const float* __restrict__ bvec,
    const float* __restrict__ sigmas, float* __restrict__ out) {
    extern __shared__ float smem[];
    u64* Wf = (u64*)smem;                       // 1024 bf16 B-fragments (8KB)
    uint32_t* zbh = (uint32_t*)(smem + 2048);   // z bf16x2 tile [128][32] (16KB)
    float* epsb = smem + 6144;                  // 2 x [128][64] fp32 (eps/z staging)
    float* red = smem + 6144 + 16384;

    const int tid = threadIdx.x;
    const int w = tid >> 5;           // 8 warps, one 16-row chain each
    const int l = tid & 31;
    const int a = l >> 2;
    const int b = l & 3;
    const int colb = 2 * b;
    const int rA = w * 16 + a;
    const int rB = rA + 8;
    const int r0 = blockIdx.x * R;
    const int b0i = r0 & (B_DIM - 1);
    const float dt = 1.0f / T_STEPS;
    const u64 dt2 = pack2(dt, dt);
    const uint32_t eps_u32 = (uint32_t)__cvta_generic_to_shared(epsb);

    // Wf: bf16 B-fragment (ks 0..3, nt 0..7, lane): u64 = (b0, b1)
    // b0 = (W[16ks+2b][8nt+a], W[16ks+2b+1][8nt+a]), b1 = rows +8,+9
#pragma unroll
    for (int it = 0; it < 1024 / NT; ++it) {
        int idx = tid + it * NT;
        int ks = idx >> 8, nt = (idx >> 5) & 7, ll = idx & 31;
        int aa = ll >> 2, bb = ll & 3;
        int k0 = 16 * ks + 2 * bb, n = 8 * nt + aa;
        uint32_t lo = bf2(W[k0 * 64 + n], W[(k0 + 1) * 64 + n]);
        uint32_t hi = bf2(W[(k0 + 8) * 64 + n], W[(k0 + 9) * 64 + n]);
        Wf[idx] = ((u64)hi << 32) | lo;
    }

    float* zs_out = out + 1;  // 4B-aligned only: scalar global stores
    u64 esq2 = 0, usq2 = 0;
    u64 up2[2][8], cd2[2][8];  // [h][nt]

    // init: z0 -> fp32 staging (buf 1) + bf16 zbh + z0^2 ; ctx drift -> regs
#pragma unroll
    for (int nt = 0; nt < 8; ++nt) {
        const int cg = colb + 8 * nt;
#pragma unroll
        for (int h = 0; h < 2; ++h) {
            const int row = h ? rB : rA;
            u64 zz = *(const u64*)(z0 + (size_t)(r0 + row) * 64 + cg);
            ffma2(esq2, zz, zz);
            up2[h][nt] = 0;
            *(u64*)(epsb + 8192 + zoff(row, cg)) = zz;  // z_prev(0) in buf 1
            float s0, s1; unpack2(zz, s0, s1);
            zbh[zbi(row, b + 4 * nt)] = bf2(s0, s1);
            cd2[h][nt] =
                *(const u64*)(g_cd + (size_t)(b0i + row) * 64 + cg);
        }
    }

    // prefetch eps(0) into buffer 0 (warp-private rows)
    {
        const float* src0 = eps + (size_t)r0 * 64;
#pragma unroll
        for (int it = 0; it < 8; ++it) {
            int id = it * 32 + l;
            int rl = id >> 4, ch = id & 15;
            int row = w * 16 + rl;
            cp16(eps_u32 + (uint32_t)(row * 64 + 4 * ((ch + (row & 7)) & 15)) * 4u,
                 src0 + (size_t)row * 64 + ch * 4);
        }
        asm volatile("cp.async.commit_group;");
    }
    __syncthreads();  // Wf + zbh + staging visible

    // z_samples[0]: coalesced from fp32 staging (buf 1)
#pragma unroll
    for (int i = 0; i < 16; ++i) {
        const int row = w * 16 + i;
        size_t go = (size_t)(r0 + row) * 64;
        float x0, x1;
        unpack2(*(const u64*)(epsb + 8192 + zoff(row, 2 * l)), x0, x1);
        __stcs(zs_out + go + 2 * l, x0);
        __stcs(zs_out + go + 2 * l + 1, x1);
    }

    u64 dtinvp2 = 0;

#pragma unroll 1
    for (int t = 0; t <= T_STEPS; ++t) {
        // ---- GEMM: drift = z_t @ W via bf16 HMMA (K=16 per mma) ----
        float acc[8][4];
#pragma unroll
        for (int nt = 0; nt < 8; ++nt)
#pragma unroll
            for (int j = 0; j < 4; ++j) acc[nt][j] = 0.f;
#pragma unroll
        for (int ks = 0; ks < 4; ++ks) {
            uint32_t a0 = zbh[zbi(rA, 8 * ks + b)];
            uint32_t a2 = zbh[zbi(rA, 8 * ks + b + 4)];
            uint32_t a1 = zbh[zbi(rB, 8 * ks + b)];
            uint32_t a3 = zbh[zbi(rB, 8 * ks + b + 4)];
#pragma unroll
            for (int nt = 0; nt < 8; ++nt) {
                u64 bb = Wf[(ks * 8 + nt) * 32 + l];
                mma_bf16(acc[nt], a0, a1, a2, a3, (uint32_t)bb,
                         (uint32_t)(bb >> 32));
            }
        }

        if (t == T_STEPS) {  // final completion of u(T-1)
#pragma unroll
            for (int nt = 0; nt < 8; ++nt)
#pragma unroll
                for (int h = 0; h < 2; ++h) {
                    u64 d2 = pack2(acc[nt][2 * h], acc[nt][2 * h + 1]);
                    u64 u2 = ffma2n(d2, dtinvp2, up2[h][nt]);
                    ffma2(usq2, u2, u2);
                }
            break;
        }

        // eps(t) must have arrived (issued end of previous step)
        asm volatile("cp.async.wait_group 0;" ::: "memory");
        __syncwarp();

        // ---- elementwise: z_prev from buf (t+1)&1, eps from buf t&1 ----
        const float sig = __ldg(sigmas + t);
        const float stdv = sig * 0.125f;
        const float inv_std = 1.0f / stdv;
        const float dtinv = dt * inv_std;
        const u64 std2 = pack2(stdv, stdv);
        const u64 dtinv2 = pack2(dtinv, dtinv);
        const u64 ndtinv2 = pack2(-dtinv, -dtinv);
        float* et = epsb + (t & 1) * 8192;        // eps(t) + zn staging
        const float* zprevb = epsb + ((t + 1) & 1) * 8192;
        const bool last = (t == T_STEPS - 1);

#pragma unroll
        for (int nt = 0; nt < 8; ++nt) {
            const int cg = colb + 8 * nt;
            float2 btv = __ldg((const float2*)(bvec + t * 64 + cg));
            u64 bt2 = pack2(btv.x, btv.y);
            u64 btd2 = mul2(bt2, dtinv2);
#pragma unroll
            for (int h = 0; h < 2; ++h) {
                const int row = h ? rB : rA;
                u64 d2 = pack2(acc[nt][2 * h], acc[nt][2 * h + 1]);
                u64 u2 = ffma2n(d2, dtinvp2, up2[h][nt]);  // complete u(t-1)
                ffma2(usq2, u2, u2);
                u64 zp2 = *(const u64*)(zprevb + zoff(row, cg));
                u64 e2 = *(const u64*)(et + zoff(row, cg));
                u64 mu2 = add2(d2, add2(cd2[h][nt], bt2));
                u64 zn2 = ffma2n(e2, std2, ffma2n(mu2, dt2, zp2));
                up2[h][nt] =
                    ffma2n(mu2, ndtinv2, add2(e2 ^ 0x8000000080000000ull, btd2));
                ffma2(esq2, e2, e2);
                if (last) ffma2(usq2, zn2, zn2);
                *(u64*)(et + zoff(row, cg)) = zn2;     // fp32 staging (z_prev t+1)
                float s0, s1; unpack2(zn2, s0, s1);
                zbh[zbi(row, b + 4 * nt)] = bf2(s0, s1);  // bf16 A-tile
            }
        }
        __syncwarp();  // staging + zbh cross-lane visible

        // ---- coalesced z_samples(t+1) stores from fp32 staging ----
        float* zo = zs_out + (size_t)(t + 1) * SB * 64;
#pragma unroll
        for (int i = 0; i < 16; ++i) {
            const int row = w * 16 + i;
            size_t go = (size_t)(r0 + row) * 64;
            float x0, x1;
            unpack2(*(const u64*)(et + zoff(row, 2 * l)), x0, x1);
            __stcs(zo + go + 2 * l, x0);
            __stcs(zo + go + 2 * l + 1, x1);
        }

        // prefetch eps(t+1) into buf (t+1)&1 (z_prev buffer now dead)
        if (t + 1 < T_STEPS) {
            const float* src = eps + ((size_t)(t + 1) * SB + (size_t)r0) * 64;
            const uint32_t dst_u32 = eps_u32 + (uint32_t)(((t + 1) & 1) * 32768);
#pragma unroll
            for (int it = 0; it < 8; ++it) {
                int id = it * 32 + l;
                int rl = id >> 4, ch = id & 15;
                int row = w * 16 + rl;
                cp16(dst_u32 + (uint32_t)(row * 64 + 4 * ((ch + (row & 7)) & 15)) * 4u,
                     src + (size_t)row * 64 + ch * 4);
            }
            asm volatile("cp.async.commit_group;");
        }
        dtinvp2 = dtinv2;
    }

    // reduce lw = (0.5/S) * (esq - usq)
    float e0, e1, q0, q1;
    unpack2(esq2, e0, e1);
    unpack2(usq2, q0, q1);
    float lw = (e0 + e1) - (q0 + q1);
#pragma unroll
    for (int off = 16; off; off >>= 1)
        lw += __shfl_down_sync(0xffffffffu, lw, off);
    if (l == 0) red[w] = lw;
    __syncthreads();
    if (tid == 0) {
        float s = 0.f;
#pragma unroll
        for (int i = 0; i < 8; ++i) s += red[i];
        atomicAdd(out, (0.5f / S_DIM) * s);
    }
}

extern "C" void kernel_launch(void* const* d_in, const int* in_sizes, int n_in,
                              void* d_out, int out_size) {
    (void)in_sizes; (void)n_in; (void)out_size;
    const float* z0      = (const float*)d_in[0];
    const float* eps     = (const float*)d_in[1];
    const float* context = (const float*)d_in[2];
    const float* W       = (const float*)d_in[3];
    const float* Wc      = (const float*)d_in[4];
    const float* bvec    = (const float*)d_in[5];
    const float* sigmas  = (const float*)d_in[6];
    float* out = (float*)d_out;

    cudaFuncSetAttribute(scan_kernel,
                         cudaFuncAttributeMaxDynamicSharedMemorySize, SMEM_BYTES);
    cudaMemsetAsync(out, 0, sizeof(float));
    ctx_kernel<<<(B_DIM * 64) / 256, 256>>>(context, Wc);
    scan_kernel<<<SB / R, NT, SMEM_BYTES>>>(z0, eps, W, bvec, sigmas, out);
}

// round 17
// speedup vs baseline: 1.4063x; 1.0973x over previous
#include <cuda_runtime.h>
#include <cstdint>

namespace {
constexpr int T_STEPS = 64;
constexpr int S_DIM = 16;
constexpr int B_DIM = 2048;
constexpr int SB = S_DIM * B_DIM;  // 32768 rows
constexpr int R = 32;              // rows per block (2 warps, 1 chain each)
constexpr int NT = 64;
// dyn smem floats: Wf 2048 (8KB) + zbh 1024 (4KB) + eps 2*2048 (16KB) + red 8
constexpr int SMEM_FLOATS = 2048 + 1024 + 2 * 2048 + 8;
constexpr int SMEM_BYTES = SMEM_FLOATS * 4;  // 28704 B
}

__device__ float g_cd[B_DIM * 64];  // context @ Wc, [B][Z]

__global__ void ctx_kernel(const float* __restrict__ context,
                           const float* __restrict__ Wc) {
    int idx = blockIdx.x * blockDim.x + threadIdx.x;
    int b = idx >> 6, z = idx & 63;
    float acc = 0.f;
#pragma unroll
    for (int c = 0; c < 64; ++c)
        acc = fmaf(context[b * 64 + c], Wc[c * 64 + z], acc);
    g_cd[idx] = acc;
}

using u64 = unsigned long long;
__device__ __forceinline__ u64 pack2(float x, float y) {
    u64 r; asm("mov.b64 %0, {%1, %2};" : "=l"(r) : "f"(x), "f"(y)); return r;
}
__device__ __forceinline__ void unpack2(u64 v, float& x, float& y) {
    asm("mov.b64 {%0, %1}, %2;" : "=f"(x), "=f"(y) : "l"(v));
}
__device__ __forceinline__ void ffma2(u64& d, u64 a, u64 b) {
    asm("fma.rn.f32x2 %0, %1, %2, %0;" : "+l"(d) : "l"(a), "l"(b));
}
__device__ __forceinline__ u64 ffma2n(u64 a, u64 b, u64 c) {
    u64 d; asm("fma.rn.f32x2 %0, %1, %2, %3;" : "=l"(d) : "l"(a), "l"(b), "l"(c));
    return d;
}
__device__ __forceinline__ u64 add2(u64 a, u64 b) {
    u64 d; asm("add.rn.f32x2 %0, %1, %2;" : "=l"(d) : "l"(a), "l"(b)); return d;
}
__device__ __forceinline__ u64 mul2(u64 a, u64 b) {
    u64 d; asm("mul.rn.f32x2 %0, %1, %2;" : "=l"(d) : "l"(a), "l"(b)); return d;
}
// m16n8k16 bf16 HMMA
__device__ __forceinline__ void mma_bf16(float* d, uint32_t a0, uint32_t a1,
                                         uint32_t a2, uint32_t a3,
                                         uint32_t b0, uint32_t b1) {
    asm("mma.sync.aligned.m16n8k16.row.col.f32.bf16.bf16.f32 "
        "{%0,%1,%2,%3}, {%4,%5,%6,%7}, {%8,%9}, {%0,%1,%2,%3};"
        : "+f"(d[0]), "+f"(d[1]), "+f"(d[2]), "+f"(d[3])
        : "r"(a0), "r"(a1), "r"(a2), "r"(a3), "r"(b0), "r"(b1));
}
// pack (lo, hi) floats -> bf16x2 u32 (lo in lower half)
__device__ __forceinline__ uint32_t bf2(float lo, float hi) {
    uint32_t p;
    asm("cvt.rn.bf16x2.f32 %0, %1, %2;" : "=r"(p) : "f"(hi), "f"(lo));
    return p;
}
__device__ __forceinline__ void cp16(uint32_t dst, const void* src) {
    asm volatile("cp.async.cg.shared.global [%0], [%1], 16;" :: "r"(dst), "l"(src));
}
// fp32 tile swizzle (floats): 16B-chunk rotate per row, 64 cols
__device__ __forceinline__ int zoff(int r, int c) {
    return r * 64 + ((c + 4 * (r & 7)) & 63);
}
// bf16x2 tile swizzle (u32 pairs): rotate per row, 32 pairs
__device__ __forceinline__ int zbi(int r, int pr) {
    return r * 32 + ((pr + 4 * (r & 7)) & 31);
}

__global__ void __launch_bounds__(NT, 8) scan_kernel(
    const float* __restrict__ z0, const float* __restrict__ eps,
    const float* __restrict__ W, const float* __restrict__ bvec,
    const float* __restrict__ sigmas, float* __restrict__ out) {
    extern __shared__ float smem[];
    u64* Wf = (u64*)smem;                       // 1024 bf16 B-fragments (8KB)
    uint32_t* zbh = (uint32_t*)(smem + 2048);   // z bf16x2 tile [32][32] (4KB)
    float* epsb = smem + 3072;                  // 2 x [32][64] fp32 (eps/z staging)
    float* red = smem + 3072 + 4096;

    const int tid = threadIdx.x;
    const int w = tid >> 5;           // 2 warps, one 16-row chain each
    const int l = tid & 31;
    const int a = l >> 2;
    const int b = l & 3;
    const int colb = 2 * b;
    const int rA = w * 16 + a;        // block-local rows 0..31
    const int rB = rA + 8;
    const int r0 = blockIdx.x * R;
    const int b0i = r0 & (B_DIM - 1);
    const float dt = 1.0f / T_STEPS;
    const u64 dt2 = pack2(dt, dt);
    const uint32_t eps_u32 = (uint32_t)__cvta_generic_to_shared(epsb);

    // Wf: bf16 B-fragment (ks 0..3, nt 0..7, lane): u64 = (b0, b1)
#pragma unroll
    for (int it = 0; it < 1024 / NT; ++it) {
        int idx = tid + it * NT;
        int ks = idx >> 8, nt = (idx >> 5) & 7, ll = idx & 31;
        int aa = ll >> 2, bb = ll & 3;
        int k0 = 16 * ks + 2 * bb, n = 8 * nt + aa;
        uint32_t lo = bf2(W[k0 * 64 + n], W[(k0 + 1) * 64 + n]);
        uint32_t hi = bf2(W[(k0 + 8) * 64 + n], W[(k0 + 9) * 64 + n]);
        Wf[idx] = ((u64)hi << 32) | lo;
    }

    float* zs_out = out + 1;  // 4B-aligned only: scalar global stores
    u64 esq2 = 0, usq2 = 0;
    u64 up2[2][8], cd2[2][8];  // [h][nt]

    // init: z0 -> fp32 staging (buf 1) + bf16 zbh + z0^2 ; ctx drift -> regs
#pragma unroll
    for (int nt = 0; nt < 8; ++nt) {
        const int cg = colb + 8 * nt;
#pragma unroll
        for (int h = 0; h < 2; ++h) {
            const int row = h ? rB : rA;
            u64 zz = *(const u64*)(z0 + (size_t)(r0 + row) * 64 + cg);
            ffma2(esq2, zz, zz);
            up2[h][nt] = 0;
            *(u64*)(epsb + 2048 + zoff(row, cg)) = zz;  // z_prev(0) in buf 1
            float s0, s1; unpack2(zz, s0, s1);
            zbh[zbi(row, b + 4 * nt)] = bf2(s0, s1);
            cd2[h][nt] =
                *(const u64*)(g_cd + (size_t)(b0i + row) * 64 + cg);
        }
    }

    // prefetch eps(0) into buffer 0 (32 rows x 16 chunks, 8 cp16/thread)
    {
        const float* src0 = eps + (size_t)r0 * 64;
#pragma unroll
        for (int it = 0; it < 8; ++it) {
            int id = it * NT + tid;          // 0..511
            int row = id >> 4, ch = id & 15;
            cp16(eps_u32 + (uint32_t)(row * 64 + 4 * ((ch + (row & 7)) & 15)) * 4u,
                 src0 + (size_t)row * 64 + ch * 4);
        }
        asm volatile("cp.async.commit_group;");
    }
    __syncthreads();  // Wf + zbh + staging visible

    // z_samples[0]: coalesced from fp32 staging (buf 1)
#pragma unroll
    for (int i = 0; i < 16; ++i) {
        const int row = w * 16 + i;
        size_t go = (size_t)(r0 + row) * 64;
        float x0, x1;
        unpack2(*(const u64*)(epsb + 2048 + zoff(row, 2 * l)), x0, x1);
        __stcs(zs_out + go + 2 * l, x0);
        __stcs(zs_out + go + 2 * l + 1, x1);
    }

    u64 dtinvp2 = 0;

#pragma unroll 1
    for (int t = 0; t <= T_STEPS; ++t) {
        // ---- GEMM: drift = z_t @ W via bf16 HMMA (K=16 per mma) ----
        float acc[8][4];
#pragma unroll
        for (int nt = 0; nt < 8; ++nt)
#pragma unroll
            for (int j = 0; j < 4; ++j) acc[nt][j] = 0.f;
#pragma unroll
        for (int ks = 0; ks < 4; ++ks) {
            uint32_t a0 = zbh[zbi(rA, 8 * ks + b)];
            uint32_t a2 = zbh[zbi(rA, 8 * ks + b + 4)];
            uint32_t a1 = zbh[zbi(rB, 8 * ks + b)];
            uint32_t a3 = zbh[zbi(rB, 8 * ks + b + 4)];
#pragma unroll
            for (int nt = 0; nt < 8; ++nt) {
                u64 bb = Wf[(ks * 8 + nt) * 32 + l];
                mma_bf16(acc[nt], a0, a1, a2, a3, (uint32_t)bb,
                         (uint32_t)(bb >> 32));
            }
        }

        if (t == T_STEPS) {  // final completion of u(T-1)
#pragma unroll
            for (int nt = 0; nt < 8; ++nt)
#pragma unroll
                for (int h = 0; h < 2; ++h) {
                    u64 d2 = pack2(acc[nt][2 * h], acc[nt][2 * h + 1]);
                    u64 u2 = ffma2n(d2, dtinvp2, up2[h][nt]);
                    ffma2(usq2, u2, u2);
                }
            break;
        }

        // eps(t) must have arrived (issued in previous step)
        asm volatile("cp.async.wait_group 0;" ::: "memory");
        __syncwarp();

        // ---- elementwise: z_prev from buf (t+1)&1, eps from buf t&1 ----
        const float sig = __ldg(sigmas + t);
        const float stdv = sig * 0.125f;
        const float inv_std = 1.0f / stdv;
        const float dtinv = dt * inv_std;
        const u64 std2 = pack2(stdv, stdv);
        const u64 dtinv2 = pack2(dtinv, dtinv);
        const u64 ndtinv2 = pack2(-dtinv, -dtinv);
        float* et = epsb + (t & 1) * 2048;        // eps(t) + zn staging
        const float* zprevb = epsb + ((t + 1) & 1) * 2048;
        const bool last = (t == T_STEPS - 1);

#pragma unroll
        for (int nt = 0; nt < 8; ++nt) {
            const int cg = colb + 8 * nt;
            float2 btv = __ldg((const float2*)(bvec + t * 64 + cg));
            u64 bt2 = pack2(btv.x, btv.y);
            u64 btd2 = mul2(bt2, dtinv2);
#pragma unroll
            for (int h = 0; h < 2; ++h) {
                const int row = h ? rB : rA;
                u64 d2 = pack2(acc[nt][2 * h], acc[nt][2 * h + 1]);
                u64 u2 = ffma2n(d2, dtinvp2, up2[h][nt]);  // complete u(t-1)
                ffma2(usq2, u2, u2);
                u64 zp2 = *(const u64*)(zprevb + zoff(row, cg));
                u64 e2 = *(const u64*)(et + zoff(row, cg));
                u64 mu2 = add2(d2, add2(cd2[h][nt], bt2));
                u64 zn2 = ffma2n(e2, std2, ffma2n(mu2, dt2, zp2));
                up2[h][nt] =
                    ffma2n(mu2, ndtinv2, add2(e2 ^ 0x8000000080000000ull, btd2));
                ffma2(esq2, e2, e2);
                if (last) ffma2(usq2, zn2, zn2);
                *(u64*)(et + zoff(row, cg)) = zn2;     // fp32 staging (z_prev t+1)
                float s0, s1; unpack2(zn2, s0, s1);
                zbh[zbi(row, b + 4 * nt)] = bf2(s0, s1);  // bf16 A-tile
            }
        }
        __syncwarp();  // staging + zbh cross-lane visible

        // prefetch eps(t+1) into buf (t+1)&1 FIRST (z_prev buffer now dead;
        // issuing before the store loop lengthens the prefetch distance)
        if (t + 1 < T_STEPS) {
            const float* src = eps + ((size_t)(t + 1) * SB + (size_t)r0) * 64;
            const uint32_t dst_u32 = eps_u32 + (uint32_t)(((t + 1) & 1) * 8192);
#pragma unroll
            for (int it = 0; it < 8; ++it) {
                int id = it * 32 + l;
                int row = w * 16 + (id >> 5) * 0 + ((id >> 4) & 1) * 0 + (id >> 4);
                // 8 iters x 32 lanes = 256 = 16 rows x 16 chunks for this warp
                int rr = w * 16 + (id >> 4);
                int ch = id & 15;
                cp16(dst_u32 + (uint32_t)(rr * 64 + 4 * ((ch + (rr & 7)) & 15)) * 4u,
                     src + (size_t)rr * 64 + ch * 4);
                (void)row;
            }
            asm volatile("cp.async.commit_group;");
        }

        // ---- coalesced z_samples(t+1) stores from fp32 staging ----
        float* zo = zs_out + (size_t)(t + 1) * SB * 64;
#pragma unroll
        for (int i = 0; i < 16; ++i) {
            const int row = w * 16 + i;
            size_t go = (size_t)(r0 + row) * 64;
            float x0, x1;
            unpack2(*(const u64*)(et + zoff(row, 2 * l)), x0, x1);
            __stcs(zo + go + 2 * l, x0);
            __stcs(zo + go + 2 * l + 1, x1);
        }
        dtinvp2 = dtinv2;
    }

    // reduce lw = (0.5/S) * (esq - usq)
    float e0, e1, q0, q1;
    unpack2(esq2, e0, e1);
    unpack2(usq2, q0, q1);
    float lw = (e0 + e1) - (q0 + q1);
#pragma unroll
    for (int off = 16; off; off >>= 1)
        lw += __shfl_down_sync(0xffffffffu, lw, off);
    if (l == 0) red[w] = lw;
    __syncthreads();
    if (tid == 0) {
        float s = red[0] + red[1];
        atomicAdd(out, (0.5f / S_DIM) * s);
    }
}

extern "C" void kernel_launch(void* const* d_in, const int* in_sizes, int n_in,
                              void* d_out, int out_size) {
    (void)in_sizes; (void)n_in; (void)out_size;
    const float* z0      = (const float*)d_in[0];
    const float* eps     = (const float*)d_in[1];
    const float* context = (const float*)d_in[2];
    const float* W       = (const float*)d_in[3];
    const float* Wc      = (const float*)d_in[4];
    const float* bvec    = (const float*)d_in[5];
    const float* sigmas  = (const float*)d_in[6];
    float* out = (float*)d_out;

    cudaFuncSetAttribute(scan_kernel,
                         cudaFuncAttributeMaxDynamicSharedMemorySize, SMEM_BYTES);
    cudaMemsetAsync(out, 0, sizeof(float));
    ctx_kernel<<<(B_DIM * 64) / 256, 256>>>(context, Wc);
    scan_kernel<<<SB / R, NT, SMEM_BYTES>>>(z0, eps, W, bvec, sigmas, out);
}